// round 1
// baseline (speedup 1.0000x reference)
#include <cuda_runtime.h>
#include <math.h>

#define BB 64
#define TT 512
#define DD 1024
#define HH 1024
#define NG 4096  // 4*H

// Scratch (allocation-free rule: __device__ globals)
__device__ float g_xproj[(size_t)BB * TT * NG];  // 512 MB: X @ W_x + b
__device__ float g_h[2][BB * HH];                // ping-pong hidden state
__device__ float g_c[BB * HH];                   // cell state

// ---------------------------------------------------------------------------
// Re-zero recurrent state every call (graph replays must be deterministic).
// ---------------------------------------------------------------------------
__global__ void init_state_kernel() {
    int i = blockIdx.x * blockDim.x + threadIdx.x;
    if (i < BB * HH) {
        g_h[0][i] = 0.0f;
        g_c[i] = 0.0f;
    }
}

// ---------------------------------------------------------------------------
// Xproj[m][n] = sum_k X[m][k] * W[k][n] + b[n]
// M = B*T = 32768, N = 4096, K = 1024.  128x128 tile, 8x8/thread, BK=8.
// ---------------------------------------------------------------------------
__global__ __launch_bounds__(256) void xproj_gemm_kernel(
    const float* __restrict__ X, const float* __restrict__ W,
    const float* __restrict__ bias) {
    __shared__ float As[8][128];  // transposed: As[k][m]
    __shared__ float Bs[8][128];

    const int m0 = blockIdx.y * 128;
    const int n0 = blockIdx.x * 128;
    const int tid = threadIdx.x;
    const int tx = tid % 16;   // 0..15 -> 8 cols each
    const int ty = tid / 16;   // 0..15 -> 8 rows each

    const int arow = tid / 2;          // 0..127
    const int acol = (tid % 2) * 4;    // 0 or 4
    const int brow = tid / 32;         // 0..7
    const int bcol = (tid % 32) * 4;   // 0..124

    float acc[8][8];
#pragma unroll
    for (int i = 0; i < 8; i++)
#pragma unroll
        for (int j = 0; j < 8; j++) acc[i][j] = 0.0f;

    for (int k0 = 0; k0 < DD; k0 += 8) {
        float4 av = *(const float4*)&X[(size_t)(m0 + arow) * DD + k0 + acol];
        As[acol + 0][arow] = av.x;
        As[acol + 1][arow] = av.y;
        As[acol + 2][arow] = av.z;
        As[acol + 3][arow] = av.w;
        *(float4*)&Bs[brow][bcol] =
            *(const float4*)&W[(size_t)(k0 + brow) * NG + n0 + bcol];
        __syncthreads();

#pragma unroll
        for (int k = 0; k < 8; k++) {
            float a[8], bv[8];
            *(float4*)&a[0] = *(float4*)&As[k][ty * 8];
            *(float4*)&a[4] = *(float4*)&As[k][ty * 8 + 4];
            *(float4*)&bv[0] = *(float4*)&Bs[k][tx * 8];
            *(float4*)&bv[4] = *(float4*)&Bs[k][tx * 8 + 4];
#pragma unroll
            for (int i = 0; i < 8; i++)
#pragma unroll
                for (int j = 0; j < 8; j++) acc[i][j] += a[i] * bv[j];
        }
        __syncthreads();
    }

#pragma unroll
    for (int i = 0; i < 8; i++) {
        int m = m0 + ty * 8 + i;
#pragma unroll
        for (int j = 0; j < 8; j += 4) {
            int n = n0 + tx * 8 + j;
            float4 o;
            o.x = acc[i][j + 0] + bias[n + 0];
            o.y = acc[i][j + 1] + bias[n + 1];
            o.z = acc[i][j + 2] + bias[n + 2];
            o.w = acc[i][j + 3] + bias[n + 3];
            *(float4*)&g_xproj[(size_t)m * NG + n] = o;
        }
    }
}

// ---------------------------------------------------------------------------
// One LSTM timestep, fused: z_h = h_prev @ W_h (M=64,N=4096,K=1024), then
// gates + state update + output write.
// Grid: 128 blocks; block bx owns h-columns [8*bx, 8*bx+8) across all 4 gates
// (32 gate-columns) and all 64 batch rows, so W_h is read exactly once/step.
// ---------------------------------------------------------------------------
__global__ __launch_bounds__(256) void lstm_step_kernel(
    const float* __restrict__ W, float* __restrict__ out, int t) {
    const float* __restrict__ hin = g_h[t & 1];
    float* __restrict__ hout = g_h[(t + 1) & 1];

    __shared__ float sh_h[32][65];  // [kk][row], padded
    __shared__ float sh_w[32][32];  // [kk][gate-col]

    const int tid = threadIdx.x;
    const int tx = tid % 32;  // gate-col within tile (g = tx/8, c = tx%8)
    const int ty = tid / 32;  // 0..7
    const int h0 = blockIdx.x * 8;

    float acc[8];
#pragma unroll
    for (int r = 0; r < 8; r++) acc[r] = 0.0f;

    const int gq = tx / 8;  // gate for W loads
    const int cq = tx % 8;  // h-col offset for W loads

    for (int k0 = 0; k0 < HH; k0 += 32) {
        // stage h chunk: sh_h[kk][row]  (global coalesced, smem conflict-free)
#pragma unroll
        for (int p = 0; p < 8; p++) {
            int row = p * 8 + ty;
            sh_h[tx][row] = hin[row * HH + k0 + tx];
        }
        // stage W chunk: rows (D + k0 + kk), cols {g*1024 + h0 + c}
#pragma unroll
        for (int p = 0; p < 4; p++) {
            int kk = p * 8 + ty;
            sh_w[kk][tx] =
                W[(size_t)(DD + k0 + kk) * NG + gq * HH + h0 + cq];
        }
        __syncthreads();

#pragma unroll
        for (int kk = 0; kk < 32; kk++) {
            float bv = sh_w[kk][tx];
#pragma unroll
            for (int r = 0; r < 8; r++)
                acc[r] += sh_h[kk][r * 8 + ty] * bv;
        }
        __syncthreads();
    }

    // exchange z through shared so each thread sees all 4 gates of an (b,h)
    float(*zsh)[32] = (float(*)[32]) & sh_h[0][0];  // 64x32 fits in sh_h
#pragma unroll
    for (int r = 0; r < 8; r++) zsh[r * 8 + ty][tx] = acc[r];
    __syncthreads();

#pragma unroll
    for (int q = 0; q < 2; q++) {
        int idx = q * 256 + tid;  // 0..511 -> (b, c)
        int b = idx / 8;
        int c = idx % 8;
        int hc = h0 + c;
        size_t mrow = (size_t)(b * TT + t) * NG;

        float zi = zsh[b][c]      + g_xproj[mrow + 0 * HH + hc];
        float zj = zsh[b][8 + c]  + g_xproj[mrow + 1 * HH + hc];
        float zf = zsh[b][16 + c] + g_xproj[mrow + 2 * HH + hc];
        float zo = zsh[b][24 + c] + g_xproj[mrow + 3 * HH + hc];

        float cprev = g_c[b * HH + hc];
        float si = 1.0f / (1.0f + __expf(-zi));
        float sf = 1.0f / (1.0f + __expf(-(zf + 1.0f)));  // FORGET_BIAS
        float so = 1.0f / (1.0f + __expf(-zo));
        float cn = cprev * sf + si * tanhf(zj);
        float hn = tanhf(cn) * so;

        g_c[b * HH + hc] = cn;
        hout[b * HH + hc] = hn;
        out[(size_t)b * TT * HH + (size_t)t * HH + hc] = hn;
    }
}

// ---------------------------------------------------------------------------
extern "C" void kernel_launch(void* const* d_in, const int* in_sizes, int n_in,
                              void* d_out, int out_size) {
    const float* x = (const float*)d_in[0];   // [B, T, D]
    const float* W = (const float*)d_in[1];   // [D+H, 4H]
    const float* b = (const float*)d_in[2];   // [4H]
    float* out = (float*)d_out;               // [B, T, H]

    init_state_kernel<<<(BB * HH + 255) / 256, 256>>>();

    dim3 ggrid(NG / 128, (BB * TT) / 128);  // (32, 256)
    xproj_gemm_kernel<<<ggrid, 256>>>(x, W, b);

    for (int t = 0; t < TT; t++) {
        lstm_step_kernel<<<HH / 8, 256>>>(W, out, t);
    }
}

// round 3
// speedup vs baseline: 1.0756x; 1.0756x over previous
#include <cuda_runtime.h>
#include <math.h>

#define BB 64
#define TT 512
#define DD 1024
#define HH 1024
#define NG 4096  // 4*H
#define KK 32    // k-chunk for the step kernel

// Scratch (allocation-free rule: __device__ globals)
__device__ float g_xproj[(size_t)BB * TT * NG];  // 512 MB: X @ W_x + b
__device__ float g_h[2][BB * HH];                // ping-pong hidden state
__device__ float g_c[BB * HH];                   // cell state

// ---------------- packed fp32x2 helpers (sm_100+/sm_103a) -------------------
typedef unsigned long long ull;

__device__ __forceinline__ ull fma2(ull a, ull b, ull c) {
    ull d;
    asm("fma.rn.f32x2 %0, %1, %2, %3;" : "=l"(d) : "l"(a), "l"(b), "l"(c));
    return d;
}
__device__ __forceinline__ ull dup2(float x) {
    ull d;
    asm("mov.b64 %0, {%1, %1};" : "=l"(d) : "f"(x));
    return d;
}
__device__ __forceinline__ void unpack2(ull v, float& lo, float& hi) {
    asm("mov.b64 {%0, %1}, %2;" : "=f"(lo), "=f"(hi) : "l"(v));
}
__device__ __forceinline__ float tanh_approx(float x) {
    float r;
    asm("tanh.approx.f32 %0, %1;" : "=f"(r) : "f"(x));
    return r;
}
__device__ __forceinline__ float sigmoid_f(float x) {
    return __fdividef(1.0f, 1.0f + __expf(-x));
}

// ---------------------------------------------------------------------------
// Re-zero recurrent state every call (graph replays must be deterministic).
// ---------------------------------------------------------------------------
__global__ void init_state_kernel() {
    int i = blockIdx.x * blockDim.x + threadIdx.x;
    if (i < BB * HH) {
        g_h[0][i] = 0.0f;
        g_c[i] = 0.0f;
    }
}

// ---------------------------------------------------------------------------
// Xproj[m][n] = sum_k X[m][k] * W[k][n] + b[n]
// M = B*T = 32768, N = 4096, K = 1024.  128x128 tile, 8x8/thread via f32x2.
// ---------------------------------------------------------------------------
__global__ __launch_bounds__(256) void xproj_gemm_kernel(
    const float* __restrict__ X, const float* __restrict__ W,
    const float* __restrict__ bias) {
    __shared__ __align__(16) float As[8][128];  // transposed: As[k][m]
    __shared__ __align__(16) float Bs[8][128];

    const int m0 = blockIdx.y * 128;
    const int n0 = blockIdx.x * 128;
    const int tid = threadIdx.x;
    const int tx = tid % 16;   // 8 cols each
    const int ty = tid / 16;   // 8 rows each

    const int arow = tid / 2;
    const int acol = (tid % 2) * 4;
    const int brow = tid / 32;
    const int bcol = (tid % 32) * 4;

    ull acc[8][4];  // [row][col-pair]
#pragma unroll
    for (int i = 0; i < 8; i++)
#pragma unroll
        for (int j = 0; j < 4; j++) acc[i][j] = 0ull;

    for (int k0 = 0; k0 < DD; k0 += 8) {
        float4 av = *(const float4*)&X[(size_t)(m0 + arow) * DD + k0 + acol];
        As[acol + 0][arow] = av.x;
        As[acol + 1][arow] = av.y;
        As[acol + 2][arow] = av.z;
        As[acol + 3][arow] = av.w;
        *(float4*)&Bs[brow][bcol] =
            *(const float4*)&W[(size_t)(k0 + brow) * NG + n0 + bcol];
        __syncthreads();

#pragma unroll
        for (int k = 0; k < 8; k++) {
            float a8[8];
            *(float4*)&a8[0] = *(float4*)&As[k][ty * 8];
            *(float4*)&a8[4] = *(float4*)&As[k][ty * 8 + 4];
            ulonglong2 b01 = *(ulonglong2*)&Bs[k][tx * 8];
            ulonglong2 b23 = *(ulonglong2*)&Bs[k][tx * 8 + 4];
#pragma unroll
            for (int i = 0; i < 8; i++) {
                ull a2 = dup2(a8[i]);
                acc[i][0] = fma2(a2, b01.x, acc[i][0]);
                acc[i][1] = fma2(a2, b01.y, acc[i][1]);
                acc[i][2] = fma2(a2, b23.x, acc[i][2]);
                acc[i][3] = fma2(a2, b23.y, acc[i][3]);
            }
        }
        __syncthreads();
    }

#pragma unroll
    for (int i = 0; i < 8; i++) {
        int m = m0 + ty * 8 + i;
        float o[8];
#pragma unroll
        for (int j = 0; j < 4; j++) unpack2(acc[i][j], o[2 * j], o[2 * j + 1]);
        int n = n0 + tx * 8;
        float4 oa, ob;
        oa.x = o[0] + bias[n + 0];
        oa.y = o[1] + bias[n + 1];
        oa.z = o[2] + bias[n + 2];
        oa.w = o[3] + bias[n + 3];
        ob.x = o[4] + bias[n + 4];
        ob.y = o[5] + bias[n + 5];
        ob.z = o[6] + bias[n + 6];
        ob.w = o[7] + bias[n + 7];
        *(float4*)&g_xproj[(size_t)m * NG + n] = oa;
        *(float4*)&g_xproj[(size_t)m * NG + n + 4] = ob;
    }
}

// ---------------------------------------------------------------------------
// One LSTM timestep: z_h = h_prev @ W_h (M=64, N=4096, K=1024) fused with the
// gate epilogue. 128 blocks x 256 threads. Block bx owns h-cols
// [8bx, 8bx+8) in all 4 gates = 32 z-cols. Warp lanes <-> 32 z-cols;
// warp w owns batch rows [8w, 8w+8) as 4 f32x2 accumulators.
// h staged transposed in smem and read via broadcast LDS.128 (2/k);
// w read via conflict-free LDS.32 (1/k). 2-stage double-buffered chunks.
// ---------------------------------------------------------------------------
__global__ __launch_bounds__(256) void lstm_step_kernel(
    const float* __restrict__ W, float* __restrict__ out, int t) {
    const float* __restrict__ hin = g_h[t & 1];
    float* __restrict__ hout = g_h[(t + 1) & 1];

    // smem: h chunks [2][KK][72 floats] (rows 0..63 at [kk][row], stride 72
    //       keeps 16B alignment for row-groups of 4), then w [2][KK][32].
    __shared__ __align__(16) float smraw[2 * KK * 72 + 2 * KK * 32];
    float* shh = smraw;                    // float view: [(buf*KK+kk)*72 + row]
    float* shw = smraw + 2 * KK * 72;      // [(buf*KK+kk)*32 + col]
    float* zs = smraw;                     // epilogue overlay: [64][33]

    const int tid = threadIdx.x;
    const int lane = tid & 31;
    const int warp = tid >> 5;
    const int h0 = blockIdx.x * 8;

    // staging maps
    const int s_row = tid >> 2, s_kq = tid & 3;                 // h: 8 k each
    const int s_kk = tid >> 3, s_q = tid & 7;                   // w: 4 cols
    const size_t s_wn = (size_t)(s_q >> 1) * HH + h0 + (s_q & 1) * 4;

    ull acc0 = 0, acc1 = 0, acc2 = 0, acc3 = 0;

    // ---- prologue: load + store chunk 0 into buffer 0 ----
    float4 ha = *(const float4*)&hin[s_row * HH + s_kq * 8];
    float4 hb = *(const float4*)&hin[s_row * HH + s_kq * 8 + 4];
    float4 wv = *(const float4*)&W[(size_t)(DD + s_kk) * NG + s_wn];
    {
        int kb = s_kq * 8;
        shh[(kb + 0) * 72 + s_row] = ha.x;
        shh[(kb + 1) * 72 + s_row] = ha.y;
        shh[(kb + 2) * 72 + s_row] = ha.z;
        shh[(kb + 3) * 72 + s_row] = ha.w;
        shh[(kb + 4) * 72 + s_row] = hb.x;
        shh[(kb + 5) * 72 + s_row] = hb.y;
        shh[(kb + 6) * 72 + s_row] = hb.z;
        shh[(kb + 7) * 72 + s_row] = hb.w;
        *(float4*)&shw[s_kk * 32 + s_q * 4] = wv;
    }
    __syncthreads();

    for (int k0 = 0; k0 < HH; k0 += KK) {
        const int buf = (k0 >> 5) & 1;
        const bool more = (k0 + KK) < HH;
        if (more) {  // prefetch next chunk into registers
            int kc = k0 + KK;
            ha = *(const float4*)&hin[s_row * HH + kc + s_kq * 8];
            hb = *(const float4*)&hin[s_row * HH + kc + s_kq * 8 + 4];
            wv = *(const float4*)&W[(size_t)(DD + kc + s_kk) * NG + s_wn];
        }

        const float* hbase = shh + (size_t)buf * KK * 72 + warp * 8;
        const float* wbase = shw + (size_t)buf * KK * 32 + lane;
#pragma unroll
        for (int kk = 0; kk < KK; kk++) {
            const ulonglong2* hp =
                reinterpret_cast<const ulonglong2*>(hbase + kk * 72);
            ulonglong2 hA = hp[0];  // rows 8w..8w+3 (broadcast)
            ulonglong2 hB = hp[1];  // rows 8w+4..8w+7
            ull w2 = dup2(wbase[kk * 32]);
            acc0 = fma2(hA.x, w2, acc0);
            acc1 = fma2(hA.y, w2, acc1);
            acc2 = fma2(hB.x, w2, acc2);
            acc3 = fma2(hB.y, w2, acc3);
        }

        if (more) {  // store prefetched chunk into the other buffer
            int nb = (buf ^ 1) * KK;
            int kb = (nb + s_kq * 8);
            shh[(kb + 0) * 72 + s_row] = ha.x;
            shh[(kb + 1) * 72 + s_row] = ha.y;
            shh[(kb + 2) * 72 + s_row] = ha.z;
            shh[(kb + 3) * 72 + s_row] = ha.w;
            shh[(kb + 4) * 72 + s_row] = hb.x;
            shh[(kb + 5) * 72 + s_row] = hb.y;
            shh[(kb + 6) * 72 + s_row] = hb.z;
            shh[(kb + 7) * 72 + s_row] = hb.w;
            *(float4*)&shw[(nb + s_kk) * 32 + s_q * 4] = wv;
        }
        __syncthreads();
    }

    // ---- exchange z through smem: zs[batch 0..63][col 0..31], stride 33 ----
    {
        float lo, hi;
        int r = warp * 8;
        unpack2(acc0, lo, hi);
        zs[(r + 0) * 33 + lane] = lo;
        zs[(r + 1) * 33 + lane] = hi;
        unpack2(acc1, lo, hi);
        zs[(r + 2) * 33 + lane] = lo;
        zs[(r + 3) * 33 + lane] = hi;
        unpack2(acc2, lo, hi);
        zs[(r + 4) * 33 + lane] = lo;
        zs[(r + 5) * 33 + lane] = hi;
        unpack2(acc3, lo, hi);
        zs[(r + 6) * 33 + lane] = lo;
        zs[(r + 7) * 33 + lane] = hi;
    }
    __syncthreads();

    // ---- gate epilogue: 512 (b, hc) pairs over 256 threads ----
#pragma unroll
    for (int q = 0; q < 2; q++) {
        int idx = q * 256 + tid;
        int b = idx >> 3;
        int c = idx & 7;
        int hc = h0 + c;
        size_t mrow = (size_t)(b * TT + t) * NG;

        float zi = zs[b * 33 + c]      + g_xproj[mrow + 0 * HH + hc];
        float zj = zs[b * 33 + 8 + c]  + g_xproj[mrow + 1 * HH + hc];
        float zf = zs[b * 33 + 16 + c] + g_xproj[mrow + 2 * HH + hc];
        float zo = zs[b * 33 + 24 + c] + g_xproj[mrow + 3 * HH + hc];

        float cprev = g_c[b * HH + hc];
        float si = sigmoid_f(zi);
        float sf = sigmoid_f(zf + 1.0f);  // FORGET_BIAS
        float so = sigmoid_f(zo);
        float cn = cprev * sf + si * tanh_approx(zj);
        float hn = tanh_approx(cn) * so;

        g_c[b * HH + hc] = cn;
        hout[b * HH + hc] = hn;
        out[(size_t)b * TT * HH + (size_t)t * HH + hc] = hn;
    }
}

// ---------------------------------------------------------------------------
extern "C" void kernel_launch(void* const* d_in, const int* in_sizes, int n_in,
                              void* d_out, int out_size) {
    const float* x = (const float*)d_in[0];   // [B, T, D]
    const float* W = (const float*)d_in[1];   // [D+H, 4H]
    const float* b = (const float*)d_in[2];   // [4H]
    float* out = (float*)d_out;               // [B, T, H]

    init_state_kernel<<<(BB * HH + 255) / 256, 256>>>();

    dim3 ggrid(NG / 128, (BB * TT) / 128);  // (32, 256)
    xproj_gemm_kernel<<<ggrid, 256>>>(x, W, b);

    for (int t = 0; t < TT; t++) {
        lstm_step_kernel<<<HH / 8, 256>>>(W, out, t);
    }
}

// round 6
// speedup vs baseline: 2.2191x; 2.0631x over previous
#include <cuda_runtime.h>
#include <cuda_bf16.h>
#include <math.h>
#include <cstdint>

#define BB 64
#define TT 512
#define DD 1024
#define HH 1024
#define NG 4096  // 4*H

// ---------------- device scratch (allocation-free rule) ---------------------
__device__ float g_xproj[(size_t)BB * TT * NG];            // 512 MB
__device__ __nv_bfloat16 g_wt_hi[(size_t)NG * HH];         // W_h^T hi  [n][k]
__device__ __nv_bfloat16 g_wt_lo[(size_t)NG * HH];         // W_h^T lo  [n][k]
__device__ __nv_bfloat16 g_h_hi[2][BB * HH];               // hidden hi, ping-pong
__device__ __nv_bfloat16 g_h_lo[2][BB * HH];               // hidden lo
__device__ float g_c[BB * HH];                             // cell state

// ---------------- helpers ---------------------------------------------------
typedef unsigned long long ull;

__device__ __forceinline__ ull fma2(ull a, ull b, ull c) {
    ull d;
    asm("fma.rn.f32x2 %0, %1, %2, %3;" : "=l"(d) : "l"(a), "l"(b), "l"(c));
    return d;
}
__device__ __forceinline__ ull dup2(float x) {
    ull d;
    asm("mov.b64 %0, {%1, %1};" : "=l"(d) : "f"(x));
    return d;
}
__device__ __forceinline__ void unpack2(ull v, float& lo, float& hi) {
    asm("mov.b64 {%0, %1}, %2;" : "=f"(lo), "=f"(hi) : "l"(v));
}
__device__ __forceinline__ float tanh_approx(float x) {
    float r;
    asm("tanh.approx.f32 %0, %1;" : "=f"(r) : "f"(x));
    return r;
}
__device__ __forceinline__ float sigmoid_f(float x) {
    return __fdividef(1.0f, 1.0f + __expf(-x));
}
__device__ __forceinline__ uint32_t smem_u32(const void* p) {
    uint32_t a;
    asm("{ .reg .u64 t; cvta.to.shared.u64 t, %1; cvt.u32.u64 %0, t; }"
        : "=r"(a) : "l"(p));
    return a;
}
__device__ __forceinline__ void ldsm4(uint32_t& r0, uint32_t& r1, uint32_t& r2,
                                      uint32_t& r3, uint32_t addr) {
    asm volatile(
        "ldmatrix.sync.aligned.m8n8.x4.shared.b16 {%0,%1,%2,%3}, [%4];"
        : "=r"(r0), "=r"(r1), "=r"(r2), "=r"(r3)
        : "r"(addr));
}
__device__ __forceinline__ void mma_tile(float* d, const uint32_t* a,
                                         const uint32_t* b) {
    asm volatile(
        "mma.sync.aligned.m16n8k16.row.col.f32.bf16.bf16.f32 "
        "{%0,%1,%2,%3}, {%4,%5,%6,%7}, {%8,%9}, {%0,%1,%2,%3};"
        : "+f"(d[0]), "+f"(d[1]), "+f"(d[2]), "+f"(d[3])
        : "r"(a[0]), "r"(a[1]), "r"(a[2]), "r"(a[3]), "r"(b[0]), "r"(b[1]));
}
#define SW128(x) ((x) ^ (((x) >> 3) & 0x70))

// ---------------- init ------------------------------------------------------
__global__ void init_state_kernel() {
    int i = blockIdx.x * blockDim.x + threadIdx.x;
    if (i < BB * HH) {
        g_h_hi[0][i] = __float2bfloat16(0.0f);
        g_h_lo[0][i] = __float2bfloat16(0.0f);
        g_c[i] = 0.0f;
    }
}

// ---------------- split + transpose W_h into bf16 hi/lo ---------------------
__global__ void wsplit_kernel(const float* __restrict__ W) {
    int k = blockIdx.x;  // 0..1023
    for (int n = threadIdx.x; n < NG; n += blockDim.x) {
        float w = W[(size_t)(DD + k) * NG + n];
        __nv_bfloat16 hi = __float2bfloat16(w);
        float lo = w - __bfloat162float(hi);
        g_wt_hi[(size_t)n * HH + k] = hi;
        g_wt_lo[(size_t)n * HH + k] = __float2bfloat16(lo);
    }
}

// ---------------- Xproj = X @ W_x + b (fp32 SIMT, unchanged) ----------------
__global__ __launch_bounds__(256) void xproj_gemm_kernel(
    const float* __restrict__ X, const float* __restrict__ W,
    const float* __restrict__ bias) {
    __shared__ __align__(16) float As[8][128];
    __shared__ __align__(16) float Bs[8][128];

    const int m0 = blockIdx.y * 128;
    const int n0 = blockIdx.x * 128;
    const int tid = threadIdx.x;
    const int tx = tid % 16;
    const int ty = tid / 16;
    const int arow = tid / 2;
    const int acol = (tid % 2) * 4;
    const int brow = tid / 32;
    const int bcol = (tid % 32) * 4;

    ull acc[8][4];
#pragma unroll
    for (int i = 0; i < 8; i++)
#pragma unroll
        for (int j = 0; j < 4; j++) acc[i][j] = 0ull;

    for (int k0 = 0; k0 < DD; k0 += 8) {
        float4 av = *(const float4*)&X[(size_t)(m0 + arow) * DD + k0 + acol];
        As[acol + 0][arow] = av.x;
        As[acol + 1][arow] = av.y;
        As[acol + 2][arow] = av.z;
        As[acol + 3][arow] = av.w;
        *(float4*)&Bs[brow][bcol] =
            *(const float4*)&W[(size_t)(k0 + brow) * NG + n0 + bcol];
        __syncthreads();

#pragma unroll
        for (int k = 0; k < 8; k++) {
            float a8[8];
            *(float4*)&a8[0] = *(float4*)&As[k][ty * 8];
            *(float4*)&a8[4] = *(float4*)&As[k][ty * 8 + 4];
            ulonglong2 b01 = *(ulonglong2*)&Bs[k][tx * 8];
            ulonglong2 b23 = *(ulonglong2*)&Bs[k][tx * 8 + 4];
#pragma unroll
            for (int i = 0; i < 8; i++) {
                ull a2 = dup2(a8[i]);
                acc[i][0] = fma2(a2, b01.x, acc[i][0]);
                acc[i][1] = fma2(a2, b01.y, acc[i][1]);
                acc[i][2] = fma2(a2, b23.x, acc[i][2]);
                acc[i][3] = fma2(a2, b23.y, acc[i][3]);
            }
        }
        __syncthreads();
    }

#pragma unroll
    for (int i = 0; i < 8; i++) {
        int m = m0 + ty * 8 + i;
        float o[8];
#pragma unroll
        for (int j = 0; j < 4; j++) unpack2(acc[i][j], o[2 * j], o[2 * j + 1]);
        int n = n0 + tx * 8;
        float4 oa, ob;
        oa.x = o[0] + bias[n + 0];
        oa.y = o[1] + bias[n + 1];
        oa.z = o[2] + bias[n + 2];
        oa.w = o[3] + bias[n + 3];
        ob.x = o[4] + bias[n + 4];
        ob.y = o[5] + bias[n + 5];
        ob.z = o[6] + bias[n + 6];
        ob.w = o[7] + bias[n + 7];
        *(float4*)&g_xproj[(size_t)m * NG + n] = oa;
        *(float4*)&g_xproj[(size_t)m * NG + n + 4] = ob;
    }
}

// ---------------------------------------------------------------------------
// HMMA LSTM step.  z = h @ W_h^T for this block's 32 n-cols, K=1024, 3
// split-precision terms via mma.sync m16n8k16 bf16 (fp32 accum).
// 128 blocks x 256 threads (8 warps).  Warp w: k-slice ks=w>>1 (4-way k
// split inside each 64-k chunk), m-half mh=w&1 (2 m16 tiles), all 4 n8
// tiles.  SW128 smem chunks double-buffered.  K-slice partials reduced
// through smem, then fused gate epilogue.
// ---------------------------------------------------------------------------
#define BUFSZ 24576
#define A_LO 8192
#define B_HI 16384
#define B_LO 20480
#define STEP_SMEM 49152
#define ZSTR 33

__global__ void __launch_bounds__(256, 1) lstm_step_mma(float* __restrict__ out,
                                                        int t) {
    extern __shared__ char smem[];
    const uint32_t sbase = smem_u32(smem);
    const int tid = threadIdx.x;
    const int warp = tid >> 5;
    const int lane = tid & 31;
    const int h0 = blockIdx.x * 8;

    const int ks = warp >> 1;  // k-slice within chunk (k16 step index)
    const int mh = warp & 1;   // m half (rows mh*32 .. mh*32+31)

    // ---- staging maps (256 threads; 16B each) ----
    const int lrow = tid >> 3;   // 0..31
    const int lkq = tid & 7;     // 16B column chunk
    const __nv_bfloat16* hh = g_h_hi[t & 1];
    const __nv_bfloat16* hl = g_h_lo[t & 1];
    const size_t a_off0 = (size_t)lrow * HH + lkq * 8;          // rows 0..31
    const size_t a_off1 = a_off0 + (size_t)32 * HH;             // rows 32..63
    const size_t b_off =
        (size_t)((lrow >> 3) * HH + h0 + (lrow & 7)) * HH + lkq * 8;
    const uint32_t a_dst0 = SW128(lrow * 128 + lkq * 16);
    const uint32_t a_dst1 = SW128((32 + lrow) * 128 + lkq * 16);
    const uint32_t b_dst = a_dst0;

    uint4 rah0, rah1, ral0, ral1, rbh, rbl;
    auto load_chunk = [&](int kc) {
        const int ko = kc * 64;
        rah0 = *(const uint4*)&hh[a_off0 + ko];
        rah1 = *(const uint4*)&hh[a_off1 + ko];
        ral0 = *(const uint4*)&hl[a_off0 + ko];
        ral1 = *(const uint4*)&hl[a_off1 + ko];
        rbh = *(const uint4*)&g_wt_hi[b_off + ko];
        rbl = *(const uint4*)&g_wt_lo[b_off + ko];
    };
    auto store_chunk = [&](int buf) {
        char* base = smem + buf * BUFSZ;
        *(uint4*)(base + a_dst0) = rah0;
        *(uint4*)(base + a_dst1) = rah1;
        *(uint4*)(base + A_LO + a_dst0) = ral0;
        *(uint4*)(base + A_LO + a_dst1) = ral1;
        *(uint4*)(base + B_HI + b_dst) = rbh;
        *(uint4*)(base + B_LO + b_dst) = rbl;
    };

    // ---- per-warp ldmatrix lane addresses (within a buffer) ----
    // A x4 matrices: (m0..7@k0),(m8..15@k0),(m0..7@k8),(m8..15@k8)
    const int a_r = (lane & 7) + ((lane >> 3) & 1) * 8;
    const int a_k = ks * 32 + (lane >> 4) * 16;
    const uint32_t offA0 = SW128((mh * 32 + a_r) * 128 + a_k);
    const uint32_t offA1 = SW128((mh * 32 + 16 + a_r) * 128 + a_k);
    // B x4 matrices: (n0..7@k0),(n0..7@k8),(n8..15@k0),(n8..15@k8)
    const int b_r = (lane & 7) + (lane >> 4) * 8;
    const int b_k = ks * 32 + ((lane >> 3) & 1) * 16;
    const uint32_t offB0 = SW128(b_r * 128 + b_k);
    const uint32_t offB1 = SW128((16 + b_r) * 128 + b_k);

    float acc[2][4][4];
#pragma unroll
    for (int mt = 0; mt < 2; mt++)
#pragma unroll
        for (int nt = 0; nt < 4; nt++)
#pragma unroll
            for (int r = 0; r < 4; r++) acc[mt][nt][r] = 0.0f;

    // ---- prologue: chunk0 -> buf0; issue loads for chunk1 ----
    load_chunk(0);
    store_chunk(0);
    load_chunk(1);
    __syncthreads();

    for (int kc = 0; kc < 16; kc++) {
        const int buf = kc & 1;
        if (kc + 1 < 16) store_chunk(buf ^ 1);  // chunk kc+1 (in regs)
        if (kc + 2 < 16) load_chunk(kc + 2);    // long-latency prefetch

        const uint32_t base = sbase + buf * BUFSZ;
        uint32_t ah[2][4], al[2][4], bh[4][2], bl[4][2];
        ldsm4(ah[0][0], ah[0][1], ah[0][2], ah[0][3], base + offA0);
        ldsm4(ah[1][0], ah[1][1], ah[1][2], ah[1][3], base + offA1);
        ldsm4(al[0][0], al[0][1], al[0][2], al[0][3], base + A_LO + offA0);
        ldsm4(al[1][0], al[1][1], al[1][2], al[1][3], base + A_LO + offA1);
        ldsm4(bh[0][0], bh[0][1], bh[1][0], bh[1][1], base + B_HI + offB0);
        ldsm4(bh[2][0], bh[2][1], bh[3][0], bh[3][1], base + B_HI + offB1);
        ldsm4(bl[0][0], bl[0][1], bl[1][0], bl[1][1], base + B_LO + offB0);
        ldsm4(bl[2][0], bl[2][1], bl[3][0], bl[3][1], base + B_LO + offB1);

        // term-major (RAW distance 8 between dependent MMAs)
#pragma unroll
        for (int mt = 0; mt < 2; mt++)
#pragma unroll
            for (int nt = 0; nt < 4; nt++) mma_tile(acc[mt][nt], ah[mt], bh[nt]);
#pragma unroll
        for (int mt = 0; mt < 2; mt++)
#pragma unroll
            for (int nt = 0; nt < 4; nt++) mma_tile(acc[mt][nt], ah[mt], bl[nt]);
#pragma unroll
        for (int mt = 0; mt < 2; mt++)
#pragma unroll
            for (int nt = 0; nt < 4; nt++) mma_tile(acc[mt][nt], al[mt], bh[nt]);

        __syncthreads();
    }

    // ---- dump k-slice partials: zpart[ks][m][n], row stride ZSTR ----
    float* zpart = (float*)smem;
#pragma unroll
    for (int mt = 0; mt < 2; mt++)
#pragma unroll
        for (int nt = 0; nt < 4; nt++) {
            int m = mh * 32 + mt * 16 + (lane >> 2);
            int n = nt * 8 + (lane & 3) * 2;
            zpart[(ks * 64 + m) * ZSTR + n] = acc[mt][nt][0];
            zpart[(ks * 64 + m) * ZSTR + n + 1] = acc[mt][nt][1];
            zpart[(ks * 64 + m + 8) * ZSTR + n] = acc[mt][nt][2];
            zpart[(ks * 64 + m + 8) * ZSTR + n + 1] = acc[mt][nt][3];
        }
    __syncthreads();

    // ---- fused gate epilogue: 512 (b, c) pairs over 256 threads ----
#pragma unroll
    for (int q = 0; q < 2; q++) {
        int idx = q * 256 + tid;
        int b = idx >> 3;
        int c = idx & 7;
        int hc = h0 + c;

        float zi = 0.0f, zj = 0.0f, zf = 0.0f, zo = 0.0f;
#pragma unroll
        for (int s = 0; s < 4; s++) {
            const float* zr = zpart + (s * 64 + b) * ZSTR;
            zi += zr[c];
            zj += zr[8 + c];
            zf += zr[16 + c];
            zo += zr[24 + c];
        }

        const float* xp = g_xproj + ((size_t)b * TT + t) * NG;
        zi += xp[hc];
        zj += xp[HH + hc];
        zf += xp[2 * HH + hc];
        zo += xp[3 * HH + hc];

        float cp = g_c[b * HH + hc];
        float si = sigmoid_f(zi);
        float sf = sigmoid_f(zf + 1.0f);  // FORGET_BIAS
        float so = sigmoid_f(zo);
        float cn = cp * sf + si * tanh_approx(zj);
        float hn = tanh_approx(cn) * so;

        g_c[b * HH + hc] = cn;
        out[((size_t)b * TT + t) * HH + hc] = hn;
        __nv_bfloat16 hi = __float2bfloat16(hn);
        g_h_hi[(t + 1) & 1][b * HH + hc] = hi;
        g_h_lo[(t + 1) & 1][b * HH + hc] =
            __float2bfloat16(hn - __bfloat162float(hi));
    }
}

// ---------------------------------------------------------------------------
extern "C" void kernel_launch(void* const* d_in, const int* in_sizes, int n_in,
                              void* d_out, int out_size) {
    const float* x = (const float*)d_in[0];   // [B, T, D]
    const float* W = (const float*)d_in[1];   // [D+H, 4H]
    const float* b = (const float*)d_in[2];   // [4H]
    float* out = (float*)d_out;               // [B, T, H]

    cudaFuncSetAttribute(lstm_step_mma,
                         cudaFuncAttributeMaxDynamicSharedMemorySize, STEP_SMEM);

    init_state_kernel<<<(BB * HH + 255) / 256, 256>>>();
    wsplit_kernel<<<HH, 256>>>(W);

    dim3 ggrid(NG / 128, (BB * TT) / 128);  // (32, 256)
    xproj_gemm_kernel<<<ggrid, 256>>>(x, W, b);

    for (int t = 0; t < TT; t++) {
        lstm_step_mma<<<128, 256, STEP_SMEM>>>(out, t);
    }
}

// round 12
// speedup vs baseline: 5.8914x; 2.6549x over previous
#include <cuda_runtime.h>
#include <cuda_bf16.h>
#include <cstdint>

#define BB 64
#define TT 512
#define DD 1024
#define HH 1024
#define NG 4096  // 4*H

// ---------------- device scratch (allocation-free rule) ---------------------
__device__ float g_xproj[(size_t)BB * TT * NG];             // 512 MB
__device__ __nv_bfloat16 g_x_hi[(size_t)BB * TT * DD];      // x split hi
__device__ __nv_bfloat16 g_x_lo[(size_t)BB * TT * DD];      // x split lo
__device__ __nv_bfloat16 g_wxt_hi[(size_t)NG * DD];         // W_x^T hi [n][k]
__device__ __nv_bfloat16 g_wxt_lo[(size_t)NG * DD];         // W_x^T lo
__device__ __nv_bfloat16 g_wt_hi[(size_t)NG * HH];          // W_h^T hi [n][k]
__device__ __nv_bfloat16 g_wt_lo[(size_t)NG * HH];          // W_h^T lo
__device__ __nv_bfloat16 g_h_hi[2][BB * HH];                // hidden hi
__device__ __nv_bfloat16 g_h_lo[2][BB * HH];                // hidden lo
__device__ float g_c[BB * HH];                              // cell state
__device__ unsigned g_bar;                                  // grid barrier

// ---------------- helpers ---------------------------------------------------
__device__ __forceinline__ float tanh_approx(float x) {
    float r;
    asm("tanh.approx.f32 %0, %1;" : "=f"(r) : "f"(x));
    return r;
}
__device__ __forceinline__ float sigmoid_f(float x) {
    return __fdividef(1.0f, 1.0f + __expf(-x));
}
__device__ __forceinline__ uint32_t smem_u32(const void* p) {
    uint32_t a;
    asm("{ .reg .u64 t; cvta.to.shared.u64 t, %1; cvt.u32.u64 %0, t; }"
        : "=r"(a) : "l"(p));
    return a;
}
__device__ __forceinline__ void ldsm4(uint32_t& r0, uint32_t& r1, uint32_t& r2,
                                      uint32_t& r3, uint32_t addr) {
    asm volatile(
        "ldmatrix.sync.aligned.m8n8.x4.shared.b16 {%0,%1,%2,%3}, [%4];"
        : "=r"(r0), "=r"(r1), "=r"(r2), "=r"(r3)
        : "r"(addr));
}
__device__ __forceinline__ void mma_tile(float* d, const uint32_t* a,
                                         const uint32_t* b) {
    asm volatile(
        "mma.sync.aligned.m16n8k16.row.col.f32.bf16.bf16.f32 "
        "{%0,%1,%2,%3}, {%4,%5,%6,%7}, {%8,%9}, {%0,%1,%2,%3};"
        : "+f"(d[0]), "+f"(d[1]), "+f"(d[2]), "+f"(d[3])
        : "r"(a[0]), "r"(a[1]), "r"(a[2]), "r"(a[3]), "r"(b[0]), "r"(b[1]));
}
__device__ __forceinline__ void cp16(uint32_t dst, const void* src) {
    asm volatile("cp.async.cg.shared.global [%0], [%1], 16;" ::"r"(dst),
                 "l"(src));
}
__device__ __forceinline__ void cp_commit() {
    asm volatile("cp.async.commit_group;");
}
template <int N>
__device__ __forceinline__ void cp_wait() {
    asm volatile("cp.async.wait_group %0;" ::"n"(N));
}
#define SW128(x) ((x) ^ (((x) >> 3) & 0x70))

// ---------------- init ------------------------------------------------------
__global__ void init_state_kernel() {
    int i = blockIdx.x * blockDim.x + threadIdx.x;
    if (i == 0) g_bar = 0u;
    if (i < BB * HH) {
        g_h_hi[0][i] = __float2bfloat16(0.0f);
        g_h_lo[0][i] = __float2bfloat16(0.0f);
        g_c[i] = 0.0f;
    }
}

// ---------------- split + transpose full W into bf16 hi/lo ------------------
__global__ void wsplit_kernel(const float* __restrict__ W) {
    int k = blockIdx.x;  // 0..2047
    for (int n = threadIdx.x; n < NG; n += blockDim.x) {
        float w = W[(size_t)k * NG + n];
        __nv_bfloat16 hi = __float2bfloat16(w);
        __nv_bfloat16 lo = __float2bfloat16(w - __bfloat162float(hi));
        if (k < DD) {
            g_wxt_hi[(size_t)n * DD + k] = hi;
            g_wxt_lo[(size_t)n * DD + k] = lo;
        } else {
            g_wt_hi[(size_t)n * HH + (k - DD)] = hi;
            g_wt_lo[(size_t)n * HH + (k - DD)] = lo;
        }
    }
}

// ---------------- split x into bf16 hi/lo -----------------------------------
__global__ void xsplit_kernel(const float* __restrict__ x) {
    size_t i = (size_t)blockIdx.x * blockDim.x + threadIdx.x;  // float4 index
    float4 v = ((const float4*)x)[i];
    float f[4] = {v.x, v.y, v.z, v.w};
    size_t b = i * 4;
#pragma unroll
    for (int j = 0; j < 4; j++) {
        __nv_bfloat16 hi = __float2bfloat16(f[j]);
        g_x_hi[b + j] = hi;
        g_x_lo[b + j] = __float2bfloat16(f[j] - __bfloat162float(hi));
    }
}

// ---------------------------------------------------------------------------
// Xproj = X @ W_x + b via split-bf16 HMMA (3 terms).  Block tile 128m x 128n,
// k-chunk 64, cp.async double-buffered.  Per-buffer regions 16 KB each
// (128 rows x 128 B): A_hi | A_lo | B_hi | B_lo = 64 KB; two buffers = 128 KB.
// 8 warps: wm=warp>>1 (m32), wn=warp&1 (n64); per warp 2 m16 x 8 n8 tiles.
// NOTE: ldmatrix addresses fold the per-ks k-offset INSIDE SW128 (adding it
// after the swizzle is wrong and can walk off the end of the region).
// ---------------------------------------------------------------------------
#define XAL 16384
#define XBH 32768
#define XBL 49152
#define XBUF 65536
#define XP_SMEM 131072

__global__ void __launch_bounds__(256, 1) xproj_mma_kernel(
    const float* __restrict__ bias) {
    extern __shared__ char smem[];
    const uint32_t sbase = smem_u32(smem);
    const int tid = threadIdx.x;
    const int warp = tid >> 5;
    const int lane = tid & 31;
    const int m0 = blockIdx.y * 128;
    const int n0 = blockIdx.x * 128;
    const int wm = warp >> 1;
    const int wn = warp & 1;

    const int srow = tid >> 3;
    const int sc16 = tid & 7;

    auto issue = [&](int kc, int buf) {
        const uint32_t db = sbase + buf * XBUF;
        const size_t ko = (size_t)kc * 64 + sc16 * 8;
#pragma unroll
        for (int p = 0; p < 4; p++) {
            int row = p * 32 + srow;
            uint32_t d = SW128(row * 128 + sc16 * 16);
            size_t sa = (size_t)(m0 + row) * DD + ko;
            size_t sb = (size_t)(n0 + row) * DD + ko;
            cp16(db + d, g_x_hi + sa);
            cp16(db + XAL + d, g_x_lo + sa);
            cp16(db + XBH + d, g_wxt_hi + sb);
            cp16(db + XBL + d, g_wxt_lo + sb);
        }
    };

    // ldmatrix row-byte bases + in-row k bases (swizzle applied per-ks below)
    const int a_r = (lane & 7) + ((lane >> 3) & 1) * 8;
    const int a_kb = (lane >> 4) * 16;
    const int b_r = (lane & 7) + (lane >> 4) * 8;
    const int b_kb = ((lane >> 3) & 1) * 16;
    uint32_t rowA[2], rowB[4];
#pragma unroll
    for (int mt = 0; mt < 2; mt++)
        rowA[mt] = (uint32_t)(wm * 32 + mt * 16 + a_r) * 128 + a_kb;
#pragma unroll
    for (int g = 0; g < 4; g++)
        rowB[g] = (uint32_t)(wn * 64 + g * 16 + b_r) * 128 + b_kb;

    float acc[2][8][4];
#pragma unroll
    for (int mt = 0; mt < 2; mt++)
#pragma unroll
        for (int nt = 0; nt < 8; nt++)
#pragma unroll
            for (int r = 0; r < 4; r++) acc[mt][nt][r] = 0.0f;

    issue(0, 0);
    cp_commit();

    for (int kc = 0; kc < 16; kc++) {
        const int buf = kc & 1;
        if (kc + 1 < 16) {
            issue(kc + 1, buf ^ 1);
            cp_commit();
            cp_wait<1>();
        } else {
            cp_wait<0>();
        }
        __syncthreads();

        const uint32_t ab = sbase + buf * XBUF;
#pragma unroll
        for (int ks = 0; ks < 4; ks++) {
            const uint32_t kb = ks * 32;
            const uint32_t oA0 = SW128(rowA[0] + kb);
            const uint32_t oA1 = SW128(rowA[1] + kb);
            uint32_t oB[4];
#pragma unroll
            for (int g = 0; g < 4; g++) oB[g] = SW128(rowB[g] + kb);

            uint32_t ah[2][4], al[2][4], bh[8][2], bl[8][2];
            ldsm4(ah[0][0], ah[0][1], ah[0][2], ah[0][3], ab + oA0);
            ldsm4(ah[1][0], ah[1][1], ah[1][2], ah[1][3], ab + oA1);
#pragma unroll
            for (int g = 0; g < 4; g++)
                ldsm4(bh[2 * g][0], bh[2 * g][1], bh[2 * g + 1][0],
                      bh[2 * g + 1][1], ab + XBH + oB[g]);
#pragma unroll
            for (int mt = 0; mt < 2; mt++)
#pragma unroll
                for (int nt = 0; nt < 8; nt++)
                    mma_tile(acc[mt][nt], ah[mt], bh[nt]);
#pragma unroll
            for (int g = 0; g < 4; g++)
                ldsm4(bl[2 * g][0], bl[2 * g][1], bl[2 * g + 1][0],
                      bl[2 * g + 1][1], ab + XBL + oB[g]);
#pragma unroll
            for (int mt = 0; mt < 2; mt++)
#pragma unroll
                for (int nt = 0; nt < 8; nt++)
                    mma_tile(acc[mt][nt], ah[mt], bl[nt]);
            ldsm4(al[0][0], al[0][1], al[0][2], al[0][3], ab + XAL + oA0);
            ldsm4(al[1][0], al[1][1], al[1][2], al[1][3], ab + XAL + oA1);
#pragma unroll
            for (int mt = 0; mt < 2; mt++)
#pragma unroll
                for (int nt = 0; nt < 8; nt++)
                    mma_tile(acc[mt][nt], al[mt], bh[nt]);
        }
        __syncthreads();
    }

    // epilogue: acc -> g_xproj (+bias)
#pragma unroll
    for (int mt = 0; mt < 2; mt++)
#pragma unroll
        for (int nt = 0; nt < 8; nt++) {
            int m = m0 + wm * 32 + mt * 16 + (lane >> 2);
            int n = n0 + wn * 64 + nt * 8 + (lane & 3) * 2;
            float b0 = bias[n], b1 = bias[n + 1];
            float2 v0 = make_float2(acc[mt][nt][0] + b0, acc[mt][nt][1] + b1);
            float2 v1 = make_float2(acc[mt][nt][2] + b0, acc[mt][nt][3] + b1);
            *(float2*)&g_xproj[(size_t)m * NG + n] = v0;
            *(float2*)&g_xproj[(size_t)(m + 8) * NG + n] = v1;
        }
}

// ---------------------------------------------------------------------------
// Persistent LSTM recurrence: 128 blocks (1/SM), all 512 steps in one launch.
// Block bx owns 32 z-cols (8 h-cols x 4 gates); W_h^T hi/lo for those cols
// preloaded into smem once (128 KB).  Per step: h staged via cp.async
// (16 chunks of 64k, double-buffered), 3-term split-bf16 HMMA, smem k-slice
// reduction, fused gate epilogue, global atomic barrier.
// (Here each warp's ks is fixed, so the full k-offset is folded inside SW128
// at offset-construction time; post-swizzle bases are all 4096-multiples.)
// ---------------------------------------------------------------------------
#define W_LO_OFF 65536
#define H_OFF 131072
#define H_BUFSZ 16384
#define H_LO 8192
#define ZP_OFF 163840
#define PERS_SMEM 197632
#define ZSTR 33

__global__ void __launch_bounds__(256, 1) lstm_persist(float* __restrict__ out) {
    extern __shared__ char smem[];
    const uint32_t sbase = smem_u32(smem);
    const int tid = threadIdx.x;
    const int warp = tid >> 5;
    const int lane = tid & 31;
    const int h0 = blockIdx.x * 8;
    const int ks = warp >> 1;  // k16 slice within 64-chunk
    const int mh = warp & 1;   // m half

    // ---- preload W_h^T (32 z-cols x 1024 k, hi+lo) into smem ----
    for (int u = tid; u < 4096; u += 256) {
        int kc = u >> 8, r = (u >> 3) & 31, c = u & 7;
        size_t so = (size_t)((r >> 3) * HH + h0 + (r & 7)) * HH + kc * 64 + c * 8;
        uint32_t d = kc * 4096 + SW128(r * 128 + c * 16);
        *(uint4*)(smem + d) = *(const uint4*)&g_wt_hi[so];
        *(uint4*)(smem + W_LO_OFF + d) = *(const uint4*)&g_wt_lo[so];
    }
    __syncthreads();

    // ---- ldmatrix fragment offsets (full k folded inside SW128) ----
    const int a_r = (lane & 7) + ((lane >> 3) & 1) * 8;
    const int a_k = ks * 32 + (lane >> 4) * 16;
    const uint32_t offA0 = SW128((mh * 32 + a_r) * 128 + a_k);
    const uint32_t offA1 = SW128((mh * 32 + 16 + a_r) * 128 + a_k);
    const int b_r = (lane & 7) + (lane >> 4) * 8;
    const int b_k = ks * 32 + ((lane >> 3) & 1) * 16;
    const uint32_t offB0 = SW128(b_r * 128 + b_k);
    const uint32_t offB1 = SW128((16 + b_r) * 128 + b_k);

    // ---- h staging map (4 cp.async of 16B per thread per chunk) ----
    const int srow = tid >> 3;
    const int sc16 = tid & 7;
    const uint32_t hd0 = SW128(srow * 128 + sc16 * 16);
    const uint32_t hd1 = SW128((srow + 32) * 128 + sc16 * 16);
    const size_t hs0 = (size_t)srow * HH + sc16 * 8;
    const size_t hs1 = hs0 + (size_t)32 * HH;

    float* zpart = (float*)(smem + ZP_OFF);

    for (int t = 0; t < TT; t++) {
        const __nv_bfloat16* hh = g_h_hi[t & 1];
        const __nv_bfloat16* hl = g_h_lo[t & 1];

        // prefetch this step's xproj gate inputs (latency hidden by k-loop)
        float xv[2][4];
#pragma unroll
        for (int q = 0; q < 2; q++) {
            int idx = q * 256 + tid;
            const float* xp =
                g_xproj + ((size_t)(idx >> 3) * TT + t) * NG + h0 + (idx & 7);
            xv[q][0] = xp[0];
            xv[q][1] = xp[HH];
            xv[q][2] = xp[2 * HH];
            xv[q][3] = xp[3 * HH];
        }

        float acc[2][4][4];
#pragma unroll
        for (int mt = 0; mt < 2; mt++)
#pragma unroll
            for (int nt = 0; nt < 4; nt++)
#pragma unroll
                for (int r = 0; r < 4; r++) acc[mt][nt][r] = 0.0f;

        // stage chunk 0
        {
            uint32_t d = sbase + H_OFF;
            cp16(d + hd0, hh + hs0);
            cp16(d + hd1, hh + hs1);
            cp16(d + H_LO + hd0, hl + hs0);
            cp16(d + H_LO + hd1, hl + hs1);
            cp_commit();
        }

        for (int kc = 0; kc < 16; kc++) {
            const int buf = kc & 1;
            if (kc + 1 < 16) {
                uint32_t d = sbase + H_OFF + (buf ^ 1) * H_BUFSZ;
                int ko = (kc + 1) * 64;
                cp16(d + hd0, hh + hs0 + ko);
                cp16(d + hd1, hh + hs1 + ko);
                cp16(d + H_LO + hd0, hl + hs0 + ko);
                cp16(d + H_LO + hd1, hl + hs1 + ko);
                cp_commit();
                cp_wait<1>();
            } else {
                cp_wait<0>();
            }
            __syncthreads();

            const uint32_t ab = sbase + H_OFF + buf * H_BUFSZ;
            const uint32_t wb = sbase + kc * 4096;
            uint32_t ah[2][4], al[2][4], bh[4][2], bl[4][2];
            ldsm4(ah[0][0], ah[0][1], ah[0][2], ah[0][3], ab + offA0);
            ldsm4(ah[1][0], ah[1][1], ah[1][2], ah[1][3], ab + offA1);
            ldsm4(al[0][0], al[0][1], al[0][2], al[0][3], ab + H_LO + offA0);
            ldsm4(al[1][0], al[1][1], al[1][2], al[1][3], ab + H_LO + offA1);
            ldsm4(bh[0][0], bh[0][1], bh[1][0], bh[1][1], wb + offB0);
            ldsm4(bh[2][0], bh[2][1], bh[3][0], bh[3][1], wb + offB1);
            ldsm4(bl[0][0], bl[0][1], bl[1][0], bl[1][1],
                  wb + W_LO_OFF + offB0);
            ldsm4(bl[2][0], bl[2][1], bl[3][0], bl[3][1],
                  wb + W_LO_OFF + offB1);

#pragma unroll
            for (int mt = 0; mt < 2; mt++)
#pragma unroll
                for (int nt = 0; nt < 4; nt++)
                    mma_tile(acc[mt][nt], ah[mt], bh[nt]);
#pragma unroll
            for (int mt = 0; mt < 2; mt++)
#pragma unroll
                for (int nt = 0; nt < 4; nt++)
                    mma_tile(acc[mt][nt], ah[mt], bl[nt]);
#pragma unroll
            for (int mt = 0; mt < 2; mt++)
#pragma unroll
                for (int nt = 0; nt < 4; nt++)
                    mma_tile(acc[mt][nt], al[mt], bh[nt]);

            __syncthreads();
        }

        // ---- k-slice partials to smem ----
#pragma unroll
        for (int mt = 0; mt < 2; mt++)
#pragma unroll
            for (int nt = 0; nt < 4; nt++) {
                int m = mh * 32 + mt * 16 + (lane >> 2);
                int n = nt * 8 + (lane & 3) * 2;
                zpart[(ks * 64 + m) * ZSTR + n] = acc[mt][nt][0];
                zpart[(ks * 64 + m) * ZSTR + n + 1] = acc[mt][nt][1];
                zpart[(ks * 64 + m + 8) * ZSTR + n] = acc[mt][nt][2];
                zpart[(ks * 64 + m + 8) * ZSTR + n + 1] = acc[mt][nt][3];
            }
        __syncthreads();

        // ---- fused gate epilogue ----
#pragma unroll
        for (int q = 0; q < 2; q++) {
            int idx = q * 256 + tid;
            int b = idx >> 3;
            int c = idx & 7;
            int hc = h0 + c;

            float zi = xv[q][0], zj = xv[q][1], zf = xv[q][2], zo = xv[q][3];
#pragma unroll
            for (int s = 0; s < 4; s++) {
                const float* zr = zpart + (s * 64 + b) * ZSTR;
                zi += zr[c];
                zj += zr[8 + c];
                zf += zr[16 + c];
                zo += zr[24 + c];
            }

            float cp = g_c[b * HH + hc];
            float si = sigmoid_f(zi);
            float sf = sigmoid_f(zf + 1.0f);  // FORGET_BIAS
            float so = sigmoid_f(zo);
            float cn = cp * sf + si * tanh_approx(zj);
            float hn = tanh_approx(cn) * so;

            g_c[b * HH + hc] = cn;
            out[((size_t)b * TT + t) * HH + hc] = hn;
            __nv_bfloat16 hi = __float2bfloat16(hn);
            g_h_hi[(t + 1) & 1][b * HH + hc] = hi;
            g_h_lo[(t + 1) & 1][b * HH + hc] =
                __float2bfloat16(hn - __bfloat162float(hi));
        }

        // ---- grid barrier (skip after last step) ----
        __threadfence();
        __syncthreads();
        if (t + 1 < TT) {
            if (tid == 0) {
                atomicAdd(&g_bar, 1u);
                unsigned target = 128u * (unsigned)(t + 1);
                while (*(volatile unsigned*)&g_bar < target) {
                }
            }
            __syncthreads();
        }
    }
}

// ---------------------------------------------------------------------------
extern "C" void kernel_launch(void* const* d_in, const int* in_sizes, int n_in,
                              void* d_out, int out_size) {
    const float* x = (const float*)d_in[0];   // [B, T, D]
    const float* W = (const float*)d_in[1];   // [D+H, 4H]
    const float* b = (const float*)d_in[2];   // [4H]
    float* out = (float*)d_out;               // [B, T, H]

    cudaFuncSetAttribute(xproj_mma_kernel,
                         cudaFuncAttributeMaxDynamicSharedMemorySize, XP_SMEM);
    cudaFuncSetAttribute(lstm_persist,
                         cudaFuncAttributeMaxDynamicSharedMemorySize, PERS_SMEM);

    init_state_kernel<<<(BB * HH + 255) / 256, 256>>>();
    wsplit_kernel<<<DD + HH, 256>>>(W);
    xsplit_kernel<<<(BB * TT * DD) / 4 / 256, 256>>>(x);

    dim3 xg(NG / 128, (BB * TT) / 128);  // (32, 256)
    xproj_mma_kernel<<<xg, 256, XP_SMEM>>>(b);

    lstm_persist<<<128, 256, PERS_SMEM>>>(out);
}

// round 13
// speedup vs baseline: 6.9585x; 1.1811x over previous
#include <cuda_runtime.h>
#include <cuda_bf16.h>
#include <cstdint>

#define BB 64
#define TT 512
#define DD 1024
#define HH 1024
#define NG 4096  // 4*H

// ---------------- device scratch (allocation-free rule) ---------------------
__device__ float g_xproj[(size_t)BB * TT * NG];             // 512 MB
__device__ __nv_bfloat16 g_x_hi[(size_t)BB * TT * DD];      // x split hi
__device__ __nv_bfloat16 g_x_lo[(size_t)BB * TT * DD];      // x split lo
__device__ __nv_bfloat16 g_wxt_hi[(size_t)NG * DD];         // W_x^T hi [n][k]
__device__ __nv_bfloat16 g_wxt_lo[(size_t)NG * DD];         // W_x^T lo
__device__ __nv_bfloat16 g_wt_hi[(size_t)NG * HH];          // W_h^T hi [n][k]
__device__ __nv_bfloat16 g_wt_lo[(size_t)NG * HH];          // W_h^T lo
__device__ __nv_bfloat16 g_h_hi[2][BB * HH];                // hidden hi
__device__ __nv_bfloat16 g_h_lo[2][BB * HH];                // hidden lo
__device__ float g_c[BB * HH];                              // cell state
__device__ unsigned g_bar;                                  // grid barrier

// ---------------- helpers ---------------------------------------------------
__device__ __forceinline__ float tanh_approx(float x) {
    float r;
    asm("tanh.approx.f32 %0, %1;" : "=f"(r) : "f"(x));
    return r;
}
__device__ __forceinline__ float sigmoid_f(float x) {
    return __fdividef(1.0f, 1.0f + __expf(-x));
}
__device__ __forceinline__ uint32_t smem_u32(const void* p) {
    uint32_t a;
    asm("{ .reg .u64 t; cvta.to.shared.u64 t, %1; cvt.u32.u64 %0, t; }"
        : "=r"(a) : "l"(p));
    return a;
}
__device__ __forceinline__ void ldsm4(uint32_t& r0, uint32_t& r1, uint32_t& r2,
                                      uint32_t& r3, uint32_t addr) {
    asm volatile(
        "ldmatrix.sync.aligned.m8n8.x4.shared.b16 {%0,%1,%2,%3}, [%4];"
        : "=r"(r0), "=r"(r1), "=r"(r2), "=r"(r3)
        : "r"(addr));
}
__device__ __forceinline__ void mma_tile(float* d, const uint32_t* a,
                                         const uint32_t* b) {
    asm volatile(
        "mma.sync.aligned.m16n8k16.row.col.f32.bf16.bf16.f32 "
        "{%0,%1,%2,%3}, {%4,%5,%6,%7}, {%8,%9}, {%0,%1,%2,%3};"
        : "+f"(d[0]), "+f"(d[1]), "+f"(d[2]), "+f"(d[3])
        : "r"(a[0]), "r"(a[1]), "r"(a[2]), "r"(a[3]), "r"(b[0]), "r"(b[1]));
}
__device__ __forceinline__ void cp16(uint32_t dst, const void* src) {
    asm volatile("cp.async.cg.shared.global [%0], [%1], 16;" ::"r"(dst),
                 "l"(src));
}
__device__ __forceinline__ void cp_commit() {
    asm volatile("cp.async.commit_group;");
}
template <int N>
__device__ __forceinline__ void cp_wait() {
    asm volatile("cp.async.wait_group %0;" ::"n"(N));
}
#define SW128(x) ((x) ^ (((x) >> 3) & 0x70))

// ---------------- init ------------------------------------------------------
__global__ void init_state_kernel() {
    int i = blockIdx.x * blockDim.x + threadIdx.x;
    if (i == 0) g_bar = 0u;
    if (i < BB * HH) {
        g_h_hi[0][i] = __float2bfloat16(0.0f);
        g_h_lo[0][i] = __float2bfloat16(0.0f);
        g_c[i] = 0.0f;
    }
}

// ---------------- split + transpose full W into bf16 hi/lo ------------------
__global__ void wsplit_kernel(const float* __restrict__ W) {
    int k = blockIdx.x;  // 0..2047
    for (int n = threadIdx.x; n < NG; n += blockDim.x) {
        float w = W[(size_t)k * NG + n];
        __nv_bfloat16 hi = __float2bfloat16(w);
        __nv_bfloat16 lo = __float2bfloat16(w - __bfloat162float(hi));
        if (k < DD) {
            g_wxt_hi[(size_t)n * DD + k] = hi;
            g_wxt_lo[(size_t)n * DD + k] = lo;
        } else {
            g_wt_hi[(size_t)n * HH + (k - DD)] = hi;
            g_wt_lo[(size_t)n * HH + (k - DD)] = lo;
        }
    }
}

// ---------------- split x into bf16 hi/lo -----------------------------------
__global__ void xsplit_kernel(const float* __restrict__ x) {
    size_t i = (size_t)blockIdx.x * blockDim.x + threadIdx.x;  // float4 index
    float4 v = ((const float4*)x)[i];
    float f[4] = {v.x, v.y, v.z, v.w};
    size_t b = i * 4;
#pragma unroll
    for (int j = 0; j < 4; j++) {
        __nv_bfloat16 hi = __float2bfloat16(f[j]);
        g_x_hi[b + j] = hi;
        g_x_lo[b + j] = __float2bfloat16(f[j] - __bfloat162float(hi));
    }
}

// ---------------------------------------------------------------------------
// Xproj = X @ W_x + b via split-bf16 HMMA (3 terms).  Block tile 128m x 128n,
// k-chunk 64, cp.async double-buffered.  Per-buffer regions 16 KB each:
// A_hi | A_lo | B_hi | B_lo = 64 KB; two buffers = 128 KB.
// 8 warps: wm=warp>>1 (m32), wn=warp&1 (n64); per warp 2 m16 x 8 n8 tiles.
// ldmatrix addresses fold the per-ks k-offset INSIDE SW128.
// ---------------------------------------------------------------------------
#define XAL 16384
#define XBH 32768
#define XBL 49152
#define XBUF 65536
#define XP_SMEM 131072

__global__ void __launch_bounds__(256, 1) xproj_mma_kernel(
    const float* __restrict__ bias) {
    extern __shared__ char smem[];
    const uint32_t sbase = smem_u32(smem);
    const int tid = threadIdx.x;
    const int warp = tid >> 5;
    const int lane = tid & 31;
    const int m0 = blockIdx.y * 128;
    const int n0 = blockIdx.x * 128;
    const int wm = warp >> 1;
    const int wn = warp & 1;

    const int srow = tid >> 3;
    const int sc16 = tid & 7;

    auto issue = [&](int kc, int buf) {
        const uint32_t db = sbase + buf * XBUF;
        const size_t ko = (size_t)kc * 64 + sc16 * 8;
#pragma unroll
        for (int p = 0; p < 4; p++) {
            int row = p * 32 + srow;
            uint32_t d = SW128(row * 128 + sc16 * 16);
            size_t sa = (size_t)(m0 + row) * DD + ko;
            size_t sb = (size_t)(n0 + row) * DD + ko;
            cp16(db + d, g_x_hi + sa);
            cp16(db + XAL + d, g_x_lo + sa);
            cp16(db + XBH + d, g_wxt_hi + sb);
            cp16(db + XBL + d, g_wxt_lo + sb);
        }
    };

    const int a_r = (lane & 7) + ((lane >> 3) & 1) * 8;
    const int a_kb = (lane >> 4) * 16;
    const int b_r = (lane & 7) + (lane >> 4) * 8;
    const int b_kb = ((lane >> 3) & 1) * 16;
    uint32_t rowA[2], rowB[4];
#pragma unroll
    for (int mt = 0; mt < 2; mt++)
        rowA[mt] = (uint32_t)(wm * 32 + mt * 16 + a_r) * 128 + a_kb;
#pragma unroll
    for (int g = 0; g < 4; g++)
        rowB[g] = (uint32_t)(wn * 64 + g * 16 + b_r) * 128 + b_kb;

    float acc[2][8][4];
#pragma unroll
    for (int mt = 0; mt < 2; mt++)
#pragma unroll
        for (int nt = 0; nt < 8; nt++)
#pragma unroll
            for (int r = 0; r < 4; r++) acc[mt][nt][r] = 0.0f;

    issue(0, 0);
    cp_commit();

    for (int kc = 0; kc < 16; kc++) {
        const int buf = kc & 1;
        if (kc + 1 < 16) {
            issue(kc + 1, buf ^ 1);
            cp_commit();
            cp_wait<1>();
        } else {
            cp_wait<0>();
        }
        __syncthreads();

        const uint32_t ab = sbase + buf * XBUF;
#pragma unroll
        for (int ks = 0; ks < 4; ks++) {
            const uint32_t kb = ks * 32;
            const uint32_t oA0 = SW128(rowA[0] + kb);
            const uint32_t oA1 = SW128(rowA[1] + kb);
            uint32_t oB[4];
#pragma unroll
            for (int g = 0; g < 4; g++) oB[g] = SW128(rowB[g] + kb);

            uint32_t ah[2][4], al[2][4], bh[8][2], bl[8][2];
            ldsm4(ah[0][0], ah[0][1], ah[0][2], ah[0][3], ab + oA0);
            ldsm4(ah[1][0], ah[1][1], ah[1][2], ah[1][3], ab + oA1);
#pragma unroll
            for (int g = 0; g < 4; g++)
                ldsm4(bh[2 * g][0], bh[2 * g][1], bh[2 * g + 1][0],
                      bh[2 * g + 1][1], ab + XBH + oB[g]);
#pragma unroll
            for (int mt = 0; mt < 2; mt++)
#pragma unroll
                for (int nt = 0; nt < 8; nt++)
                    mma_tile(acc[mt][nt], ah[mt], bh[nt]);
#pragma unroll
            for (int g = 0; g < 4; g++)
                ldsm4(bl[2 * g][0], bl[2 * g][1], bl[2 * g + 1][0],
                      bl[2 * g + 1][1], ab + XBL + oB[g]);
#pragma unroll
            for (int mt = 0; mt < 2; mt++)
#pragma unroll
                for (int nt = 0; nt < 8; nt++)
                    mma_tile(acc[mt][nt], ah[mt], bl[nt]);
            ldsm4(al[0][0], al[0][1], al[0][2], al[0][3], ab + XAL + oA0);
            ldsm4(al[1][0], al[1][1], al[1][2], al[1][3], ab + XAL + oA1);
#pragma unroll
            for (int mt = 0; mt < 2; mt++)
#pragma unroll
                for (int nt = 0; nt < 8; nt++)
                    mma_tile(acc[mt][nt], al[mt], bh[nt]);
        }
        __syncthreads();
    }

#pragma unroll
    for (int mt = 0; mt < 2; mt++)
#pragma unroll
        for (int nt = 0; nt < 8; nt++) {
            int m = m0 + wm * 32 + mt * 16 + (lane >> 2);
            int n = n0 + wn * 64 + nt * 8 + (lane & 3) * 2;
            float b0 = bias[n], b1 = bias[n + 1];
            float2 v0 = make_float2(acc[mt][nt][0] + b0, acc[mt][nt][1] + b1);
            float2 v1 = make_float2(acc[mt][nt][2] + b0, acc[mt][nt][3] + b1);
            *(float2*)&g_xproj[(size_t)m * NG + n] = v0;
            *(float2*)&g_xproj[(size_t)(m + 8) * NG + n] = v1;
        }
}

// ---------------------------------------------------------------------------
// Persistent LSTM recurrence: 128 blocks (1/SM), all 512 steps in one launch.
// W_h^T hi/lo for the block's 32 z-cols resident in smem (128 KB).
// Per step: h staged via a 4-slot cp.async ring (loads issued 3 chunks ahead;
// one __syncthreads per chunk; always-commit keeps wait_group<2> exact),
// 3-term split-bf16 HMMA, smem k-slice reduction (aliased onto the dead
// h-ring), fused gate epilogue, xv prefetch for t+1, global atomic barrier.
// ---------------------------------------------------------------------------
#define W_LO_OFF 65536
#define H_OFF 131072
#define H_SLOT 16384
#define H_LO 8192
#define PERS_SMEM 196608
#define ZSTR 33

__global__ void __launch_bounds__(256, 1) lstm_persist(float* __restrict__ out) {
    extern __shared__ char smem[];
    const uint32_t sbase = smem_u32(smem);
    const int tid = threadIdx.x;
    const int warp = tid >> 5;
    const int lane = tid & 31;
    const int h0 = blockIdx.x * 8;
    const int ks = warp >> 1;  // k16 slice within 64-chunk
    const int mh = warp & 1;   // m half

    // ---- preload W_h^T (32 z-cols x 1024 k, hi+lo) into smem ----
    for (int u = tid; u < 4096; u += 256) {
        int kc = u >> 8, r = (u >> 3) & 31, c = u & 7;
        size_t so = (size_t)((r >> 3) * HH + h0 + (r & 7)) * HH + kc * 64 + c * 8;
        uint32_t d = kc * 4096 + SW128(r * 128 + c * 16);
        *(uint4*)(smem + d) = *(const uint4*)&g_wt_hi[so];
        *(uint4*)(smem + W_LO_OFF + d) = *(const uint4*)&g_wt_lo[so];
    }
    __syncthreads();

    // ---- ldmatrix fragment offsets (full k folded inside SW128) ----
    const int a_r = (lane & 7) + ((lane >> 3) & 1) * 8;
    const int a_k = ks * 32 + (lane >> 4) * 16;
    const uint32_t offA0 = SW128((mh * 32 + a_r) * 128 + a_k);
    const uint32_t offA1 = SW128((mh * 32 + 16 + a_r) * 128 + a_k);
    const int b_r = (lane & 7) + (lane >> 4) * 8;
    const int b_k = ks * 32 + ((lane >> 3) & 1) * 16;
    const uint32_t offB0 = SW128(b_r * 128 + b_k);
    const uint32_t offB1 = SW128((16 + b_r) * 128 + b_k);

    // ---- h staging map (4 cp.async of 16B per thread per chunk) ----
    const int srow = tid >> 3;
    const int sc16 = tid & 7;
    const uint32_t hd0 = SW128(srow * 128 + sc16 * 16);
    const uint32_t hd1 = SW128((srow + 32) * 128 + sc16 * 16);
    const size_t hs0 = (size_t)srow * HH + sc16 * 8;
    const size_t hs1 = hs0 + (size_t)32 * HH;

    float* zpart = (float*)(smem + H_OFF);  // alias: h-ring dead at reduce time

    // ---- xv prefetch (xproj gate inputs for step t) ----
    float xv[2][4];
    auto load_xv = [&](int t) {
#pragma unroll
        for (int q = 0; q < 2; q++) {
            int idx = q * 256 + tid;
            const float* xp =
                g_xproj + ((size_t)(idx >> 3) * TT + t) * NG + h0 + (idx & 7);
            xv[q][0] = xp[0];
            xv[q][1] = xp[HH];
            xv[q][2] = xp[2 * HH];
            xv[q][3] = xp[3 * HH];
        }
    };
    load_xv(0);

    for (int t = 0; t < TT; t++) {
        const __nv_bfloat16* hh = g_h_hi[t & 1];
        const __nv_bfloat16* hl = g_h_lo[t & 1];

        auto stage = [&](int kc) {  // issue chunk kc into slot kc&3
            uint32_t d = sbase + H_OFF + (kc & 3) * H_SLOT;
            int ko = kc * 64;
            cp16(d + hd0, hh + hs0 + ko);
            cp16(d + hd1, hh + hs1 + ko);
            cp16(d + H_LO + hd0, hl + hs0 + ko);
            cp16(d + H_LO + hd1, hl + hs1 + ko);
        };

        float acc[2][4][4];
#pragma unroll
        for (int mt = 0; mt < 2; mt++)
#pragma unroll
            for (int nt = 0; nt < 4; nt++)
#pragma unroll
                for (int r = 0; r < 4; r++) acc[mt][nt][r] = 0.0f;

        // prologue: chunks 0..2 -> slots 0..2 (3 commit groups)
        stage(0);
        cp_commit();
        stage(1);
        cp_commit();
        stage(2);
        cp_commit();

        for (int kc = 0; kc < 16; kc++) {
            cp_wait<2>();     // group kc complete (always-commit discipline)
            __syncthreads();  // all warps done with chunk kc-1 (slot (kc+3)&3)
            if (kc + 3 < 16) stage(kc + 3);
            cp_commit();  // empty commits at tail keep the arithmetic exact

            const uint32_t ab = sbase + H_OFF + (kc & 3) * H_SLOT;
            const uint32_t wb = sbase + kc * 4096;
            uint32_t ah[2][4], al[2][4], bh[4][2], bl[4][2];
            ldsm4(ah[0][0], ah[0][1], ah[0][2], ah[0][3], ab + offA0);
            ldsm4(ah[1][0], ah[1][1], ah[1][2], ah[1][3], ab + offA1);
            ldsm4(al[0][0], al[0][1], al[0][2], al[0][3], ab + H_LO + offA0);
            ldsm4(al[1][0], al[1][1], al[1][2], al[1][3], ab + H_LO + offA1);
            ldsm4(bh[0][0], bh[0][1], bh[1][0], bh[1][1], wb + offB0);
            ldsm4(bh[2][0], bh[2][1], bh[3][0], bh[3][1], wb + offB1);
            ldsm4(bl[0][0], bl[0][1], bl[1][0], bl[1][1],
                  wb + W_LO_OFF + offB0);
            ldsm4(bl[2][0], bl[2][1], bl[3][0], bl[3][1],
                  wb + W_LO_OFF + offB1);

#pragma unroll
            for (int mt = 0; mt < 2; mt++)
#pragma unroll
                for (int nt = 0; nt < 4; nt++)
                    mma_tile(acc[mt][nt], ah[mt], bh[nt]);
#pragma unroll
            for (int mt = 0; mt < 2; mt++)
#pragma unroll
                for (int nt = 0; nt < 4; nt++)
                    mma_tile(acc[mt][nt], ah[mt], bl[nt]);
#pragma unroll
            for (int mt = 0; mt < 2; mt++)
#pragma unroll
                for (int nt = 0; nt < 4; nt++)
                    mma_tile(acc[mt][nt], al[mt], bh[nt]);
        }
        __syncthreads();  // protect zpart alias from in-flight chunk reads

        // ---- k-slice partials to smem ----
#pragma unroll
        for (int mt = 0; mt < 2; mt++)
#pragma unroll
            for (int nt = 0; nt < 4; nt++) {
                int m = mh * 32 + mt * 16 + (lane >> 2);
                int n = nt * 8 + (lane & 3) * 2;
                zpart[(ks * 64 + m) * ZSTR + n] = acc[mt][nt][0];
                zpart[(ks * 64 + m) * ZSTR + n + 1] = acc[mt][nt][1];
                zpart[(ks * 64 + m + 8) * ZSTR + n] = acc[mt][nt][2];
                zpart[(ks * 64 + m + 8) * ZSTR + n + 1] = acc[mt][nt][3];
            }
        __syncthreads();

        // ---- fused gate epilogue ----
#pragma unroll
        for (int q = 0; q < 2; q++) {
            int idx = q * 256 + tid;
            int b = idx >> 3;
            int c = idx & 7;
            int hc = h0 + c;

            float zi = xv[q][0], zj = xv[q][1], zf = xv[q][2], zo = xv[q][3];
#pragma unroll
            for (int s = 0; s < 4; s++) {
                const float* zr = zpart + (s * 64 + b) * ZSTR;
                zi += zr[c];
                zj += zr[8 + c];
                zf += zr[16 + c];
                zo += zr[24 + c];
            }

            float cp = g_c[b * HH + hc];
            float si = sigmoid_f(zi);
            float sf = sigmoid_f(zf + 1.0f);  // FORGET_BIAS
            float so = sigmoid_f(zo);
            float cn = cp * sf + si * tanh_approx(zj);
            float hn = tanh_approx(cn) * so;

            g_c[b * HH + hc] = cn;
            out[((size_t)b * TT + t) * HH + hc] = hn;
            __nv_bfloat16 hi = __float2bfloat16(hn);
            g_h_hi[(t + 1) & 1][b * HH + hc] = hi;
            g_h_lo[(t + 1) & 1][b * HH + hc] =
                __float2bfloat16(hn - __bfloat162float(hi));
        }

        // prefetch next step's xv before the barrier (independent of h)
        if (t + 1 < TT) load_xv(t + 1);

        // ---- grid barrier (skip after last step) ----
        __threadfence();
        __syncthreads();
        if (t + 1 < TT) {
            if (tid == 0) {
                atomicAdd(&g_bar, 1u);
                unsigned target = 128u * (unsigned)(t + 1);
                while (*(volatile unsigned*)&g_bar < target) {
                }
            }
            __syncthreads();
        }
    }
}

// ---------------------------------------------------------------------------
extern "C" void kernel_launch(void* const* d_in, const int* in_sizes, int n_in,
                              void* d_out, int out_size) {
    const float* x = (const float*)d_in[0];   // [B, T, D]
    const float* W = (const float*)d_in[1];   // [D+H, 4H]
    const float* b = (const float*)d_in[2];   // [4H]
    float* out = (float*)d_out;               // [B, T, H]

    cudaFuncSetAttribute(xproj_mma_kernel,
                         cudaFuncAttributeMaxDynamicSharedMemorySize, XP_SMEM);
    cudaFuncSetAttribute(lstm_persist,
                         cudaFuncAttributeMaxDynamicSharedMemorySize, PERS_SMEM);

    init_state_kernel<<<(BB * HH + 255) / 256, 256>>>();
    wsplit_kernel<<<DD + HH, 256>>>(W);
    xsplit_kernel<<<(BB * TT * DD) / 4 / 256, 256>>>(x);

    dim3 xg(NG / 128, (BB * TT) / 128);  // (32, 256)
    xproj_mma_kernel<<<xg, 256, XP_SMEM>>>(b);

    lstm_persist<<<128, 256, PERS_SMEM>>>(out);
}